// round 3
// baseline (speedup 1.0000x reference)
#include <cuda_runtime.h>

// Fixed problem shape: N=100000 nodes, F=128 features, OUT=16, E=640000 edges.
// Scratch: per-node AB table. Row n (32 floats = 128 B, line-aligned):
//   [0..15]  = A[n][o] = dot(h[n], W[o, 0:128])     (W_u part)
//   [16..31] = B[n][o] = dot(h[n], W[o, 128:256])   (W_v part)
#define NODES_MAX 100000
__device__ __align__(16) float g_AB[(size_t)NODES_MAX * 32];

// Packed dual-FMA: acc.{lo,hi} += a.{lo,hi} * w.{lo,hi}  (fp32x2, sm_100+)
__device__ __forceinline__ void fma2(unsigned long long& acc,
                                     unsigned long long a,
                                     unsigned long long w) {
    asm("fma.rn.f32x2 %0, %1, %2, %0;" : "+l"(acc) : "l"(a), "l"(w));
}

// ---------------------------------------------------------------------------
// Kernel 1: per-node GEMM  AB[n] = h[n] @ Wt   (Wt is 128 x 32)
// One thread per node; Wt staged in shared, broadcast LDS.128 reads.
// ---------------------------------------------------------------------------
__global__ __launch_bounds__(256)
void node_gemm_kernel(const float* __restrict__ h,
                      const float* __restrict__ W,   // [16][256] row-major
                      int N) {
    // Ws[k*32 + o]: o<16 -> W[o][k] (W_u), o>=16 -> W[o-16][128+k] (W_v)
    __shared__ __align__(16) float Ws[128 * 32];
    const int tid = threadIdx.x;
    #pragma unroll
    for (int i = tid; i < 128 * 32; i += 256) {
        int k = i >> 5, o = i & 31;
        Ws[i] = (o < 16) ? W[o * 256 + k] : W[(o - 16) * 256 + 128 + k];
    }
    __syncthreads();

    const int n = blockIdx.x * 256 + tid;
    if (n >= N) return;

    const float4* h4 = reinterpret_cast<const float4*>(h) + (size_t)n * 32;

    unsigned long long acc[16];   // 16 packed f32x2 = 32 fp32 accumulators
    #pragma unroll
    for (int i = 0; i < 16; ++i) acc[i] = 0ull;

    #pragma unroll 4
    for (int k4 = 0; k4 < 32; ++k4) {
        const float4 hv = h4[k4];
        const float hk[4] = {hv.x, hv.y, hv.z, hv.w};
        #pragma unroll
        for (int kk = 0; kk < 4; ++kk) {
            unsigned long long h2;
            asm("mov.b64 %0, {%1, %1};" : "=l"(h2) : "f"(hk[kk]));
            const ulonglong2* wrow =
                reinterpret_cast<const ulonglong2*>(&Ws[(k4 * 4 + kk) << 5]);
            #pragma unroll
            for (int j = 0; j < 8; ++j) {
                ulonglong2 w = wrow[j];     // LDS.128 (warp-broadcast)
                fma2(acc[2 * j],     h2, w.x);
                fma2(acc[2 * j + 1], h2, w.y);
            }
        }
    }

    // Store 128 B row as 8 x STG.128 (already packed pairs)
    ulonglong2* o2 = reinterpret_cast<ulonglong2*>(
        reinterpret_cast<unsigned long long*>(g_AB) + (size_t)n * 16);
    #pragma unroll
    for (int j = 0; j < 8; ++j) {
        ulonglong2 v;
        v.x = acc[2 * j];
        v.y = acc[2 * j + 1];
        o2[j] = v;
    }
}

// ---------------------------------------------------------------------------
// Kernel 2: per-edge combine  out[e] = A[src[e]] + B[dst[e]] + b
// 4 threads per edge, one float4 each -> coalesced 128 B output stores.
// NOTE: harness materializes the reference's int64 indices as int32.
// ---------------------------------------------------------------------------
__global__ __launch_bounds__(256)
void edge_combine_kernel(const int* __restrict__ src,
                         const int* __restrict__ dst,
                         const float* __restrict__ b,
                         float* __restrict__ out,
                         int E) {
    const int idx = blockIdx.x * 256 + threadIdx.x;
    if (idx >= E * 4) return;
    const int e = idx >> 2;
    const int q = idx & 3;

    const int s = __ldg(&src[e]);
    const int d = __ldg(&dst[e]);

    const float4 av = *reinterpret_cast<const float4*>(
        &g_AB[(size_t)s * 32 + q * 4]);          // A part: bytes 0..63 of row
    const float4 bv = *reinterpret_cast<const float4*>(
        &g_AB[(size_t)d * 32 + 16 + q * 4]);     // B part: bytes 64..127
    const float4 bias = __ldg(reinterpret_cast<const float4*>(b) + q);

    float4 r;
    r.x = av.x + bv.x + bias.x;
    r.y = av.y + bv.y + bias.y;
    r.z = av.z + bv.z + bias.z;
    r.w = av.w + bv.w + bias.w;

    reinterpret_cast<float4*>(out)[idx] = r;     // out[e*16 + q*4 .. +3]
}

// ---------------------------------------------------------------------------
extern "C" void kernel_launch(void* const* d_in, const int* in_sizes, int n_in,
                              void* d_out, int out_size) {
    const float* h   = (const float*)d_in[0];
    const int*   src = (const int*)d_in[1];
    const int*   dst = (const int*)d_in[2];
    const float* W   = (const float*)d_in[3];
    const float* b   = (const float*)d_in[4];
    float*       out = (float*)d_out;

    const int OUT = in_sizes[4];             // 16
    const int F   = in_sizes[3] / (2 * OUT); // 128
    const int N   = in_sizes[0] / F;         // 100000
    const int E   = in_sizes[1];             // 640000

    node_gemm_kernel<<<(N + 255) / 256, 256>>>(h, W, N);

    const int total = E * 4;
    edge_combine_kernel<<<(total + 255) / 256, 256>>>(src, dst, b, out, E);
}

// round 4
// speedup vs baseline: 1.0667x; 1.0667x over previous
#include <cuda_runtime.h>

// N=100000 nodes, F=128, OUT=16, E=640000.
// AB table row n (32 floats = 128 B): [0..15]=A[n]+bias (W_u part), [16..31]=B[n] (W_v part)
#define NODES_PAD 100096   // 782 blocks * 128
__device__ __align__(16) float g_AB[(size_t)NODES_PAD * 32];

// Packed dual-FMA: acc += a * w   (fp32x2)
__device__ __forceinline__ void fma2(unsigned long long& acc,
                                     unsigned long long a,
                                     unsigned long long w) {
    asm("fma.rn.f32x2 %0, %1, %2, %0;" : "+l"(acc) : "l"(a), "l"(w));
}
__device__ __forceinline__ void add2(unsigned long long& acc, unsigned long long v) {
    asm("add.rn.f32x2 %0, %0, %1;" : "+l"(acc) : "l"(v));
}
#define DUP2(d, f) asm("mov.b64 %0, {%1, %1};" : "=l"(d) : "f"(f))

// ---------------------------------------------------------------------------
// Kernel 1: register-tiled node GEMM.
// Block = 256 threads computes a 128-node x 32-out tile.
// Thread (nn = tid>>3, on = tid&7) owns nodes [nn*4,+4) x outs [on*4,+4).
// Per k: 1 LDS.128 (h of 4 nodes, k-major smem) + 1 LDS.128 (W 4 outs) -> 16 MACs.
// ---------------------------------------------------------------------------
__global__ __launch_bounds__(256)
void node_gemm_kernel(const float* __restrict__ h,
                      const float* __restrict__ W,   // [16][256] row-major
                      const float* __restrict__ b,   // [16]
                      int N) {
    __shared__ __align__(16) float Ws[128 * 32];  // [k][o]; o<16 -> W_u, o>=16 -> W_v
    __shared__ __align__(16) float hs[32 * 128];  // k-chunk major: [kk][node]

    const int tid = threadIdx.x;
    #pragma unroll
    for (int i = tid; i < 128 * 32; i += 256) {
        int k = i >> 5, o = i & 31;
        Ws[i] = (o < 16) ? W[o * 256 + k] : W[(o - 16) * 256 + 128 + k];
    }

    const int on = tid & 7;          // out-group
    const int nn = tid >> 3;         // node-group
    const int node_base = blockIdx.x * 128;

    // h staging map: thread loads 16 consecutive k of one node (coalesced LDG.128 x4)
    const int ld_node = tid >> 1;            // 0..127
    const int ld_koff = (tid & 1) * 16;      // 0 or 16 within 32-k chunk
    int gnode = node_base + ld_node;
    if (gnode >= N) gnode = N - 1;           // clamp for tail block
    const float4* hrow = reinterpret_cast<const float4*>(h + (size_t)gnode * 128);

    unsigned long long acc[4][2];            // [node][out-pair], packed f32x2
    #pragma unroll
    for (int i = 0; i < 4; ++i) { acc[i][0] = 0ull; acc[i][1] = 0ull; }

    for (int c = 0; c < 4; ++c) {            // k chunks of 32
        float4 v[4];
        #pragma unroll
        for (int i = 0; i < 4; ++i) v[i] = hrow[(c * 32 + ld_koff) / 4 + i];

        __syncthreads();                     // previous chunk fully consumed
        #pragma unroll
        for (int i = 0; i < 4; ++i) {
            const int kk = ld_koff + i * 4;
            hs[(kk + 0) * 128 + ld_node] = v[i].x;
            hs[(kk + 1) * 128 + ld_node] = v[i].y;
            hs[(kk + 2) * 128 + ld_node] = v[i].z;
            hs[(kk + 3) * 128 + ld_node] = v[i].w;
        }
        __syncthreads();

        #pragma unroll
        for (int kk = 0; kk < 32; ++kk) {
            const float4 hv = *reinterpret_cast<const float4*>(&hs[kk * 128 + nn * 4]);
            const ulonglong2 wv = *reinterpret_cast<const ulonglong2*>(
                &Ws[(c * 32 + kk) * 32 + on * 4]);
            unsigned long long h0, h1, h2, h3;
            DUP2(h0, hv.x); DUP2(h1, hv.y); DUP2(h2, hv.z); DUP2(h3, hv.w);
            fma2(acc[0][0], h0, wv.x); fma2(acc[0][1], h0, wv.y);
            fma2(acc[1][0], h1, wv.x); fma2(acc[1][1], h1, wv.y);
            fma2(acc[2][0], h2, wv.x); fma2(acc[2][1], h2, wv.y);
            fma2(acc[3][0], h3, wv.x); fma2(acc[3][1], h3, wv.y);
        }
    }

    // Fold bias into the A half (outs 0..15 <-> on < 4).
    unsigned long long b01 = 0ull, b23 = 0ull;
    if (on < 4) {
        const float4 bb = __ldg(reinterpret_cast<const float4*>(b) + on);
        asm("mov.b64 %0, {%1, %2};" : "=l"(b01) : "f"(bb.x), "f"(bb.y));
        asm("mov.b64 %0, {%1, %2};" : "=l"(b23) : "f"(bb.z), "f"(bb.w));
    }

    #pragma unroll
    for (int i = 0; i < 4; ++i) {
        const int n = node_base + nn * 4 + i;
        if (n < N) {
            add2(acc[i][0], b01);
            add2(acc[i][1], b23);
            ulonglong2 st;
            st.x = acc[i][0];
            st.y = acc[i][1];
            *reinterpret_cast<ulonglong2*>(&g_AB[(size_t)n * 32 + on * 4]) = st;
        }
    }
}

// ---------------------------------------------------------------------------
// Kernel 2: per-edge combine  out[e] = (A+bias)[src[e]] + B[dst[e]]
// 4 threads per edge, one float4 each -> coalesced 128 B output stores.
// Indices arrive as int32 from the harness.
// ---------------------------------------------------------------------------
__global__ __launch_bounds__(256)
void edge_combine_kernel(const int* __restrict__ src,
                         const int* __restrict__ dst,
                         float* __restrict__ out,
                         int E) {
    const int idx = blockIdx.x * 256 + threadIdx.x;
    if (idx >= E * 4) return;
    const int e = idx >> 2;
    const int q = idx & 3;

    const int s = __ldg(&src[e]);
    const int d = __ldg(&dst[e]);

    const float4 av = *reinterpret_cast<const float4*>(
        &g_AB[(size_t)s * 32 + q * 4]);          // A(+bias): bytes 0..63
    const float4 bv = *reinterpret_cast<const float4*>(
        &g_AB[(size_t)d * 32 + 16 + q * 4]);     // B: bytes 64..127

    float4 r;
    r.x = av.x + bv.x;
    r.y = av.y + bv.y;
    r.z = av.z + bv.z;
    r.w = av.w + bv.w;

    reinterpret_cast<float4*>(out)[idx] = r;
}

// ---------------------------------------------------------------------------
extern "C" void kernel_launch(void* const* d_in, const int* in_sizes, int n_in,
                              void* d_out, int out_size) {
    const float* h   = (const float*)d_in[0];
    const int*   src = (const int*)d_in[1];
    const int*   dst = (const int*)d_in[2];
    const float* W   = (const float*)d_in[3];
    const float* b   = (const float*)d_in[4];
    float*       out = (float*)d_out;

    const int OUT = in_sizes[4];             // 16
    const int F   = in_sizes[3] / (2 * OUT); // 128
    const int N   = in_sizes[0] / F;         // 100000
    const int E   = in_sizes[1];             // 640000

    node_gemm_kernel<<<(N + 127) / 128, 256>>>(h, W, b, N);

    const int total = E * 4;
    edge_combine_kernel<<<(total + 255) / 256, 256>>>(src, dst, out, E);
}